// round 11
// baseline (speedup 1.0000x reference)
#include <cuda_runtime.h>
#include <cuda_fp16.h>
#include <cstdint>

// GCMCGraphConv fused kernel v11 (sm_100a)
//
//   pa = sigmoid(feat @ prob_w.T); rs = sigmoid(feat @ rsw.T)
//   rf = (feat @ review_w.T) * rs
//   out[d] += (weight[src]*pa + rf) * cj[src] * ci[d]
//
// v11 = v10 (151us, best; occ 36%, regs 80) on a register diet to reach
// 4 blocks/SM (32 warps): all row addressing via u32 byte offsets from
// shared bases (feat 410MB, weight/out 25.6MB all < 4GB), meta kept
// transient. Identical math + memory traffic to v10.

#define OUT_DIM 64
#define THREADS 256
#define WARPS   8
#define TILE_E  256
#define NT      9

// per-warp: cbuf 32 rows x 32 half2 (4096B) + rbuf 32xfloat4 (512B) + ccb (128B)
#define WBUF_BYTES  (4096 + 512 + 128)
#define BTAB_OFF    (WARPS * WBUF_BYTES)
#define SMEM_BYTES  (BTAB_OFF + NT * 4 * 32 * 8)

__device__ __forceinline__ void mma16816(float c[4],
    unsigned a0, unsigned a1, unsigned a2, unsigned a3,
    unsigned b0, unsigned b1)
{
    asm volatile(
      "mma.sync.aligned.m16n8k16.row.col.f32.f16.f16.f32 "
      "{%0,%1,%2,%3}, {%4,%5,%6,%7}, {%8,%9}, {%0,%1,%2,%3};\n"
      : "+f"(c[0]), "+f"(c[1]), "+f"(c[2]), "+f"(c[3])
      : "r"(a0), "r"(a1), "r"(a2), "r"(a3), "r"(b0), "r"(b1));
}

__device__ __forceinline__ void red_add_v4(const float* p, float4 v) {
    asm volatile("red.global.add.v4.f32 [%0], {%1,%2,%3,%4};"
                 :: "l"(p), "f"(v.x), "f"(v.y), "f"(v.z), "f"(v.w) : "memory");
}

__device__ __forceinline__ unsigned packh2(float a, float b) {
    __half2 h = __floats2half2_rn(a, b);
    return *(unsigned*)&h;
}
__device__ __forceinline__ float2 h2f2(unsigned u) {
    __half2 h = *(__half2*)&u;
    return __half22float2(h);
}
__device__ __forceinline__ float sigmoidf_(float x) {
    return 1.f / (1.f + __expf(-x));
}

__global__ void __launch_bounds__(THREADS, 4)
gcmc_kernel(const float* __restrict__ weight,      // [N_SRC,64]
            const float* __restrict__ prob_w,      // [64]
            const float* __restrict__ rsw,         // [64]
            const float* __restrict__ review_w,    // [64,64]
            const float* __restrict__ feat,        // [E,64]
            const float* __restrict__ cj,          // [N_SRC]
            const float* __restrict__ ci,          // [N_DST]
            const int*   __restrict__ src_idx,     // [E]
            const int*   __restrict__ dst_idx,     // [E]
            float* __restrict__ out,               // [N_DST,64]
            int E, int n_tiles)
{
    extern __shared__ char smraw[];

    const int tid  = threadIdx.x;
    const int lane = tid & 31;
    const int warp = tid >> 5;
    const int g    = lane >> 2;   // 0..7
    const int t    = lane & 3;    // 0..3

    char*   wbase = smraw + warp * WBUF_BYTES;
    unsigned* cbuf = (unsigned*)wbase;                 // [32 rows][32 half2]
    float4* rbuf = (float4*)(wbase + 4096);            // [32] {pa*cc, rs*cc, src, dst}
    float*  ccb  = (float*)(wbase + 4096 + 512);       // [32] cj*ci
    uint2 (*Btab)[4][32] = (uint2(*)[4][32])(smraw + BTAB_OFF);

    // ---- build B fragments once (fp16, single-pass; k = 16ks+4t+{0..3}) ----
    for (int i = tid; i < NT * 4 * 32; i += THREADS) {
        int l  = i & 31;
        int ks = (i >> 5) & 3;
        int nt = i >> 7;
        int gg = l >> 2, tt = l & 3;
        int k0 = 16 * ks + 4 * tt;
        float w0 = 0.f, w1 = 0.f, w2 = 0.f, w3 = 0.f;
        if (nt < 8) {
            const float* W = review_w + (nt * 8 + gg) * OUT_DIM;
            w0 = W[k0]; w1 = W[k0 + 1]; w2 = W[k0 + 2]; w3 = W[k0 + 3];
        } else if (gg == 0) {   // gate col 64 = pa (prob_w)
            w0 = prob_w[k0]; w1 = prob_w[k0 + 1];
            w2 = prob_w[k0 + 2]; w3 = prob_w[k0 + 3];
        } else if (gg == 1) {   // gate col 65 = rs (review_score_w)
            w0 = rsw[k0]; w1 = rsw[k0 + 1];
            w2 = rsw[k0 + 2]; w3 = rsw[k0 + 3];
        }
        Btab[nt][ks][l] = make_uint2(packh2(w0, w1), packh2(w2, w3));
    }
    __syncthreads();

    const int rb = warp * 32;
    const int half = lane >> 4;      // epilogue: 0/1 -> which of 2 rows
    const int j    = lane & 15;      // epilogue: 8B chunk (4 cols) within row
    const char* featc   = (const char*)feat;
    const char* weightc = (const char*)weight;
    const char* outc    = (const char*)out;

    for (int tile = blockIdx.x; tile < n_tiles; tile += gridDim.x) {
        const int e0 = tile * TILE_E + rb;

        // ---- meta: 1 edge per lane -> ccb, rbuf.zw (src,dst) ----
        {
            int e = e0 + lane;
            bool v = e < E;
            int ec = v ? e : E - 1;
            int s_ = src_idx[ec], d_ = dst_idx[ec];
            float cc = v ? cj[s_] * ci[d_] : 0.f;
            ccb[lane] = cc;
            ((float2*)&rbuf[lane])[1] =
                make_float2(__int_as_float(s_), __int_as_float(d_));
        }
        __syncwarp();

        // ---- load ALL A fragments for this tile (16-deep LDG burst) ----
        // u32 byte offsets: feat is [E,64] f32 = E*256B < 4GB
        unsigned a[2][4][4];   // [mt][ks][slot], packed fp16x2
        {
            unsigned offA[2], offB[2];
            #pragma unroll
            for (int mt = 0; mt < 2; mt++) {
                int ea = e0 + 16 * mt + g;
                int eb = ea + 8;
                offA[mt] = (unsigned)(ea < E ? ea : E - 1) * 256u;
                offB[mt] = (unsigned)(eb < E ? eb : E - 1) * 256u;
            }
            #pragma unroll
            for (int ks = 0; ks < 4; ks++) {
                const unsigned ko = (unsigned)(16 * ks + 4 * t) * 4u;
                #pragma unroll
                for (int mt = 0; mt < 2; mt++) {
                    float4 v0 = *(const float4*)(featc + offA[mt] + ko);  // row g
                    float4 v1 = *(const float4*)(featc + offB[mt] + ko);  // row g+8
                    a[mt][ks][0] = packh2(v0.x, v0.y);
                    a[mt][ks][1] = packh2(v1.x, v1.y);
                    a[mt][ks][2] = packh2(v0.z, v0.w);
                    a[mt][ks][3] = packh2(v1.z, v1.w);
                }
            }
        }

        // ---- GEMM nt-outer, single-pass: 8 accum floats live ----
        #pragma unroll
        for (int nt = 0; nt < NT; nt++) {
            float c0[4] = {0.f, 0.f, 0.f, 0.f};
            float c1[4] = {0.f, 0.f, 0.f, 0.f};
            #pragma unroll
            for (int ks = 0; ks < 4; ks++) {
                uint2 b = Btab[nt][ks][lane];
                mma16816(c0, a[0][ks][0], a[0][ks][1], a[0][ks][2], a[0][ks][3], b.x, b.y);
                mma16816(c1, a[1][ks][0], a[1][ks][1], a[1][ks][2], a[1][ks][3], b.x, b.y);
            }
            if (nt < 8) {
                // slot ch2 = (4nt + t + 4*(r&3)) & 31; one half2 (2 cols) per slot
                {
                    const int r0 = g;
                    const int ch2 = (4 * nt + t + 4 * (r0 & 3)) & 31;
                    cbuf[r0 * 32 + ch2]       = packh2(c0[0], c0[1]);
                    cbuf[(r0 + 8) * 32 + ch2] = packh2(c0[2], c0[3]);
                }
                {
                    const int r0 = 16 + g;
                    const int ch2 = (4 * nt + t + 4 * (r0 & 3)) & 31;
                    cbuf[r0 * 32 + ch2]       = packh2(c1[0], c1[1]);
                    cbuf[(r0 + 8) * 32 + ch2] = packh2(c1[2], c1[3]);
                }
            } else if (t == 0) {
                // gate tile: cols 64(pa), 65(rs); fold sigmoid * cjci
                {
                    const int r0 = g, r1 = g + 8;
                    float cc0 = ccb[r0], cc1 = ccb[r1];
                    ((float2*)&rbuf[r0])[0] = make_float2(
                        sigmoidf_(c0[0]) * cc0, sigmoidf_(c0[1]) * cc0);
                    ((float2*)&rbuf[r1])[0] = make_float2(
                        sigmoidf_(c0[2]) * cc1, sigmoidf_(c0[3]) * cc1);
                }
                {
                    const int r0 = 16 + g, r1 = 24 + g;
                    float cc0 = ccb[r0], cc1 = ccb[r1];
                    ((float2*)&rbuf[r0])[0] = make_float2(
                        sigmoidf_(c1[0]) * cc0, sigmoidf_(c1[1]) * cc0);
                    ((float2*)&rbuf[r1])[0] = make_float2(
                        sigmoidf_(c1[2]) * cc1, sigmoidf_(c1[3]) * cc1);
                }
            }
        }
        __syncwarp();

        // ---- row-major epilogue: 2 edge rows per warp instruction ----
        #pragma unroll
        for (int i = 0; i < 16; i++) {
            const int r = 2 * i + half;
            // slots {2j, 2j+1} = 2 half2 = 4 columns
            uint2 cp = *(const uint2*)(cbuf + r * 32 + 2 * j);
            float2 lo = h2f2(cp.x), hi = h2f2(cp.y);
            const int cn2 = (2 * j - 4 * (r & 3)) & 31;   // even, no pair wrap
            const unsigned colb = (unsigned)(2 * cn2) * 4u;  // 16B-aligned byte off
            float4 q = rbuf[r];                            // {paC, rsC, src, dst}
            unsigned soff = (unsigned)__float_as_int(q.z) * 256u;
            unsigned doff = (unsigned)__float_as_int(q.w) * 256u;
            float4 wv = *(const float4*)(weightc + soff + colb);
            float4 o;
            o.x = fmaf(wv.x, q.x, lo.x * q.y);
            o.y = fmaf(wv.y, q.x, lo.y * q.y);
            o.z = fmaf(wv.z, q.x, hi.x * q.y);
            o.w = fmaf(wv.w, q.x, hi.y * q.y);
            red_add_v4((const float*)(outc + doff + colb), o);
        }
        __syncwarp();   // buffers reused next tile (warp-private)
    }
}

extern "C" void kernel_launch(void* const* d_in, const int* in_sizes, int n_in,
                              void* d_out, int out_size) {
    const float* weight   = (const float*)d_in[0];
    const float* prob_w   = (const float*)d_in[1];
    const float* rsw      = (const float*)d_in[2];
    const float* review_w = (const float*)d_in[3];
    const float* feat     = (const float*)d_in[4];
    const float* cj       = (const float*)d_in[5];
    const float* ci       = (const float*)d_in[6];
    const int*   src_idx  = (const int*)d_in[7];
    const int*   dst_idx  = (const int*)d_in[8];
    float* out = (float*)d_out;

    const int E = in_sizes[4] / OUT_DIM;
    const int n_tiles = (E + TILE_E - 1) / TILE_E;

    cudaMemsetAsync(d_out, 0, (size_t)out_size * sizeof(float), 0);

    static int smem_set = 0;
    if (!smem_set) {
        cudaFuncSetAttribute(gcmc_kernel,
                             cudaFuncAttributeMaxDynamicSharedMemorySize,
                             SMEM_BYTES);
        smem_set = 1;
    }

    int grid = n_tiles < 592 ? n_tiles : 592;   // 4 persistent blocks / SM
    gcmc_kernel<<<grid, THREADS, SMEM_BYTES, 0>>>(
        weight, prob_w, rsw, review_w, feat, cj, ci, src_idx, dst_idx,
        out, E, n_tiles);
}

// round 12
// speedup vs baseline: 1.2055x; 1.2055x over previous
#include <cuda_runtime.h>
#include <cuda_fp16.h>
#include <cstdint>

// GCMCGraphConv fused kernel v12 (sm_100a)
//
//   pa = sigmoid(feat @ prob_w.T); rs = sigmoid(feat @ rsw.T)
//   rf = (feat @ review_w.T) * rs
//   out[d] += (weight[src]*pa + rf) * cj[src] * ci[d]
//
// v12 = v10 (151us, best) byte-identical structure + latency hints only:
//  - prefetch.global.L2 of the NEXT tile's 8KB feat slice (2 instr/lane)
//    issued between GEMM and epilogue -> next A-burst hits L2 not DRAM.
//  - idx lines for the next tile prefetched too.
//  - feat loads use __ldcs (evict-first): 410MB streamed once stops
//    thrashing L2, protecting weight/out/cj/ci gather residency.
// v11 (64-reg diet) regressed to 190us: occ-3/80-reg is the RF optimum.

#define OUT_DIM 64
#define THREADS 256
#define WARPS   8
#define TILE_E  256
#define NT      9

// per-warp: cbuf 32 rows x 32 half2 (4096B) + rbuf 32xfloat4 (512B) + ccb (128B)
#define WBUF_BYTES  (4096 + 512 + 128)
#define BTAB_OFF    (WARPS * WBUF_BYTES)
#define SMEM_BYTES  (BTAB_OFF + NT * 4 * 32 * 8)

__device__ __forceinline__ void mma16816(float c[4],
    unsigned a0, unsigned a1, unsigned a2, unsigned a3,
    unsigned b0, unsigned b1)
{
    asm volatile(
      "mma.sync.aligned.m16n8k16.row.col.f32.f16.f16.f32 "
      "{%0,%1,%2,%3}, {%4,%5,%6,%7}, {%8,%9}, {%0,%1,%2,%3};\n"
      : "+f"(c[0]), "+f"(c[1]), "+f"(c[2]), "+f"(c[3])
      : "r"(a0), "r"(a1), "r"(a2), "r"(a3), "r"(b0), "r"(b1));
}

__device__ __forceinline__ void red_add_v4(float* p, float4 v) {
    asm volatile("red.global.add.v4.f32 [%0], {%1,%2,%3,%4};"
                 :: "l"(p), "f"(v.x), "f"(v.y), "f"(v.z), "f"(v.w) : "memory");
}

__device__ __forceinline__ void prefetch_l2(const void* p) {
    asm volatile("prefetch.global.L2 [%0];" :: "l"(p));
}

__device__ __forceinline__ unsigned packh2(float a, float b) {
    __half2 h = __floats2half2_rn(a, b);
    return *(unsigned*)&h;
}
__device__ __forceinline__ float2 h2f2(unsigned u) {
    __half2 h = *(__half2*)&u;
    return __half22float2(h);
}
__device__ __forceinline__ float sigmoidf_(float x) {
    return 1.f / (1.f + __expf(-x));
}

__global__ void __launch_bounds__(THREADS, 3)
gcmc_kernel(const float* __restrict__ weight,      // [N_SRC,64]
            const float* __restrict__ prob_w,      // [64]
            const float* __restrict__ rsw,         // [64]
            const float* __restrict__ review_w,    // [64,64]
            const float* __restrict__ feat,        // [E,64]
            const float* __restrict__ cj,          // [N_SRC]
            const float* __restrict__ ci,          // [N_DST]
            const int*   __restrict__ src_idx,     // [E]
            const int*   __restrict__ dst_idx,     // [E]
            float* __restrict__ out,               // [N_DST,64]
            int E, int n_tiles)
{
    extern __shared__ char smraw[];

    const int tid  = threadIdx.x;
    const int lane = tid & 31;
    const int warp = tid >> 5;
    const int g    = lane >> 2;   // 0..7
    const int t    = lane & 3;    // 0..3

    char*   wbase = smraw + warp * WBUF_BYTES;
    unsigned* cbuf = (unsigned*)wbase;                 // [32 rows][32 half2]
    float4* rbuf = (float4*)(wbase + 4096);            // [32] {pa*cc, rs*cc, src, dst}
    float*  ccb  = (float*)(wbase + 4096 + 512);       // [32] cj*ci
    uint2 (*Btab)[4][32] = (uint2(*)[4][32])(smraw + BTAB_OFF);

    // ---- build B fragments once (fp16, single-pass; k = 16ks+4t+{0..3}) ----
    for (int i = tid; i < NT * 4 * 32; i += THREADS) {
        int l  = i & 31;
        int ks = (i >> 5) & 3;
        int nt = i >> 7;
        int gg = l >> 2, tt = l & 3;
        int k0 = 16 * ks + 4 * tt;
        float w0 = 0.f, w1 = 0.f, w2 = 0.f, w3 = 0.f;
        if (nt < 8) {
            const float* W = review_w + (nt * 8 + gg) * OUT_DIM;
            w0 = W[k0]; w1 = W[k0 + 1]; w2 = W[k0 + 2]; w3 = W[k0 + 3];
        } else if (gg == 0) {   // gate col 64 = pa (prob_w)
            w0 = prob_w[k0]; w1 = prob_w[k0 + 1];
            w2 = prob_w[k0 + 2]; w3 = prob_w[k0 + 3];
        } else if (gg == 1) {   // gate col 65 = rs (review_score_w)
            w0 = rsw[k0]; w1 = rsw[k0 + 1];
            w2 = rsw[k0 + 2]; w3 = rsw[k0 + 3];
        }
        Btab[nt][ks][l] = make_uint2(packh2(w0, w1), packh2(w2, w3));
    }
    __syncthreads();

    const int rb = warp * 32;
    const int half = lane >> 4;      // epilogue: 0/1 -> which of 2 rows
    const int j    = lane & 15;      // epilogue: 8B chunk (4 cols) within row
    const int estep = gridDim.x * TILE_E;

    for (int tile = blockIdx.x; tile < n_tiles; tile += gridDim.x) {
        const int e0 = tile * TILE_E + rb;

        // ---- meta: 1 edge per lane -> ccb, rbuf.zw (src,dst) ----
        {
            int e = e0 + lane;
            bool v = e < E;
            int ec = v ? e : E - 1;
            int s_ = src_idx[ec], d_ = dst_idx[ec];
            float cc = v ? cj[s_] * ci[d_] : 0.f;
            ccb[lane] = cc;
            ((float2*)&rbuf[lane])[1] =
                make_float2(__int_as_float(s_), __int_as_float(d_));
        }
        __syncwarp();

        // ---- load ALL A fragments for this tile (16-deep LDG.cs burst) ----
        unsigned a[2][4][4];   // [mt][ks][slot], packed fp16x2
        {
            const float* fA[2];
            const float* fB[2];
            #pragma unroll
            for (int mt = 0; mt < 2; mt++) {
                int ea = e0 + 16 * mt + g;
                int eb = ea + 8;
                fA[mt] = feat + (size_t)(ea < E ? ea : E - 1) * OUT_DIM;
                fB[mt] = feat + (size_t)(eb < E ? eb : E - 1) * OUT_DIM;
            }
            #pragma unroll
            for (int ks = 0; ks < 4; ks++) {
                const int ko = 16 * ks + 4 * t;
                #pragma unroll
                for (int mt = 0; mt < 2; mt++) {
                    float4 v0 = __ldcs((const float4*)(fA[mt] + ko));  // row g
                    float4 v1 = __ldcs((const float4*)(fB[mt] + ko));  // row g+8
                    a[mt][ks][0] = packh2(v0.x, v0.y);
                    a[mt][ks][1] = packh2(v1.x, v1.y);
                    a[mt][ks][2] = packh2(v0.z, v0.w);
                    a[mt][ks][3] = packh2(v1.z, v1.w);
                }
            }
        }

        // ---- GEMM nt-outer, single-pass: 8 accum floats live ----
        #pragma unroll
        for (int nt = 0; nt < NT; nt++) {
            float c0[4] = {0.f, 0.f, 0.f, 0.f};
            float c1[4] = {0.f, 0.f, 0.f, 0.f};
            #pragma unroll
            for (int ks = 0; ks < 4; ks++) {
                uint2 b = Btab[nt][ks][lane];
                mma16816(c0, a[0][ks][0], a[0][ks][1], a[0][ks][2], a[0][ks][3], b.x, b.y);
                mma16816(c1, a[1][ks][0], a[1][ks][1], a[1][ks][2], a[1][ks][3], b.x, b.y);
            }
            if (nt < 8) {
                // slot ch2 = (4nt + t + 4*(r&3)) & 31; one half2 (2 cols) per slot
                {
                    const int r0 = g;
                    const int ch2 = (4 * nt + t + 4 * (r0 & 3)) & 31;
                    cbuf[r0 * 32 + ch2]       = packh2(c0[0], c0[1]);
                    cbuf[(r0 + 8) * 32 + ch2] = packh2(c0[2], c0[3]);
                }
                {
                    const int r0 = 16 + g;
                    const int ch2 = (4 * nt + t + 4 * (r0 & 3)) & 31;
                    cbuf[r0 * 32 + ch2]       = packh2(c1[0], c1[1]);
                    cbuf[(r0 + 8) * 32 + ch2] = packh2(c1[2], c1[3]);
                }
            } else if (t == 0) {
                // gate tile: cols 64(pa), 65(rs); fold sigmoid * cjci
                {
                    const int r0 = g, r1 = g + 8;
                    float cc0 = ccb[r0], cc1 = ccb[r1];
                    ((float2*)&rbuf[r0])[0] = make_float2(
                        sigmoidf_(c0[0]) * cc0, sigmoidf_(c0[1]) * cc0);
                    ((float2*)&rbuf[r1])[0] = make_float2(
                        sigmoidf_(c0[2]) * cc1, sigmoidf_(c0[3]) * cc1);
                }
                {
                    const int r0 = 16 + g, r1 = 24 + g;
                    float cc0 = ccb[r0], cc1 = ccb[r1];
                    ((float2*)&rbuf[r0])[0] = make_float2(
                        sigmoidf_(c1[0]) * cc0, sigmoidf_(c1[1]) * cc0);
                    ((float2*)&rbuf[r1])[0] = make_float2(
                        sigmoidf_(c1[2]) * cc1, sigmoidf_(c1[3]) * cc1);
                }
            }
        }

        // ---- prefetch NEXT tile's slice into L2 (covers A-burst latency) ----
        {
            int en = e0 + estep + lane;
            if (en < E) {
                const char* p = (const char*)feat + (size_t)en * 256;
                prefetch_l2(p);
                prefetch_l2(p + 128);
                prefetch_l2(src_idx + en);
                prefetch_l2(dst_idx + en);
            }
        }
        __syncwarp();

        // ---- row-major epilogue: 2 edge rows per warp instruction ----
        #pragma unroll
        for (int i = 0; i < 16; i++) {
            const int r = 2 * i + half;
            // slots {2j, 2j+1} = 2 half2 = 4 columns
            uint2 cp = *(const uint2*)(cbuf + r * 32 + 2 * j);
            float2 lo = h2f2(cp.x), hi = h2f2(cp.y);
            const int cn2 = (2 * j - 4 * (r & 3)) & 31;   // even, no pair wrap
            const int col = 2 * cn2;                       // 16B aligned
            float4 q = rbuf[r];                            // {paC, rsC, src, dst}
            int sx = __float_as_int(q.z);
            int dx = __float_as_int(q.w);
            float4 wv = *(const float4*)(weight + (size_t)sx * OUT_DIM + col);
            float4 o;
            o.x = fmaf(wv.x, q.x, lo.x * q.y);
            o.y = fmaf(wv.y, q.x, lo.y * q.y);
            o.z = fmaf(wv.z, q.x, hi.x * q.y);
            o.w = fmaf(wv.w, q.x, hi.y * q.y);
            red_add_v4(out + (size_t)dx * OUT_DIM + col, o);
        }
        __syncwarp();   // buffers reused next tile (warp-private)
    }
}

extern "C" void kernel_launch(void* const* d_in, const int* in_sizes, int n_in,
                              void* d_out, int out_size) {
    const float* weight   = (const float*)d_in[0];
    const float* prob_w   = (const float*)d_in[1];
    const float* rsw      = (const float*)d_in[2];
    const float* review_w = (const float*)d_in[3];
    const float* feat     = (const float*)d_in[4];
    const float* cj       = (const float*)d_in[5];
    const float* ci       = (const float*)d_in[6];
    const int*   src_idx  = (const int*)d_in[7];
    const int*   dst_idx  = (const int*)d_in[8];
    float* out = (float*)d_out;

    const int E = in_sizes[4] / OUT_DIM;
    const int n_tiles = (E + TILE_E - 1) / TILE_E;

    cudaMemsetAsync(d_out, 0, (size_t)out_size * sizeof(float), 0);

    static int smem_set = 0;
    if (!smem_set) {
        cudaFuncSetAttribute(gcmc_kernel,
                             cudaFuncAttributeMaxDynamicSharedMemorySize,
                             SMEM_BYTES);
        smem_set = 1;
    }

    int grid = n_tiles < 444 ? n_tiles : 444;   // 3 persistent blocks / SM
    gcmc_kernel<<<grid, THREADS, SMEM_BYTES, 0>>>(
        weight, prob_w, rsw, review_w, feat, cj, ci, src_idx, dst_idx,
        out, E, n_tiles);
}

// round 14
// speedup vs baseline: 1.2478x; 1.0351x over previous
#include <cuda_runtime.h>
#include <cuda_fp16.h>
#include <cstdint>

// GCMCGraphConv fused kernel v13 (sm_100a)  [resubmit: R13 bench was an
// infra failure ("container failed twice"), no kernel signal]
//
//   pa = sigmoid(feat @ prob_w.T); rs = sigmoid(feat @ rsw.T)
//   rf = (feat @ review_w.T) * rs
//   out[d] += (weight[src]*pa + rf) * cj[src] * ci[d]
//
// v13 = v10 (151us, best) + __ldcs on the feat A-burst ONLY.
// v12 showed ldcs+prefetch cut DRAM traffic 668->549MB but the per-lane
// prefetch instructions added ~128 wf/warp-tile of LSU work (net -7us).
// This keeps the traffic win (evict-first streaming of the 410MB feat
// protects weight/out/cj/ci L2 residency for the gathers/reductions) and
// drops the prefetch cost. Everything else byte-identical to v10.

#define OUT_DIM 64
#define THREADS 256
#define WARPS   8
#define TILE_E  256
#define NT      9

// per-warp: cbuf 32 rows x 32 half2 (4096B) + rbuf 32xfloat4 (512B) + ccb (128B)
#define WBUF_BYTES  (4096 + 512 + 128)
#define BTAB_OFF    (WARPS * WBUF_BYTES)
#define SMEM_BYTES  (BTAB_OFF + NT * 4 * 32 * 8)

__device__ __forceinline__ void mma16816(float c[4],
    unsigned a0, unsigned a1, unsigned a2, unsigned a3,
    unsigned b0, unsigned b1)
{
    asm volatile(
      "mma.sync.aligned.m16n8k16.row.col.f32.f16.f16.f32 "
      "{%0,%1,%2,%3}, {%4,%5,%6,%7}, {%8,%9}, {%0,%1,%2,%3};\n"
      : "+f"(c[0]), "+f"(c[1]), "+f"(c[2]), "+f"(c[3])
      : "r"(a0), "r"(a1), "r"(a2), "r"(a3), "r"(b0), "r"(b1));
}

__device__ __forceinline__ void red_add_v4(float* p, float4 v) {
    asm volatile("red.global.add.v4.f32 [%0], {%1,%2,%3,%4};"
                 :: "l"(p), "f"(v.x), "f"(v.y), "f"(v.z), "f"(v.w) : "memory");
}

__device__ __forceinline__ unsigned packh2(float a, float b) {
    __half2 h = __floats2half2_rn(a, b);
    return *(unsigned*)&h;
}
__device__ __forceinline__ float2 h2f2(unsigned u) {
    __half2 h = *(__half2*)&u;
    return __half22float2(h);
}
__device__ __forceinline__ float sigmoidf_(float x) {
    return 1.f / (1.f + __expf(-x));
}

__global__ void __launch_bounds__(THREADS, 3)
gcmc_kernel(const float* __restrict__ weight,      // [N_SRC,64]
            const float* __restrict__ prob_w,      // [64]
            const float* __restrict__ rsw,         // [64]
            const float* __restrict__ review_w,    // [64,64]
            const float* __restrict__ feat,        // [E,64]
            const float* __restrict__ cj,          // [N_SRC]
            const float* __restrict__ ci,          // [N_DST]
            const int*   __restrict__ src_idx,     // [E]
            const int*   __restrict__ dst_idx,     // [E]
            float* __restrict__ out,               // [N_DST,64]
            int E, int n_tiles)
{
    extern __shared__ char smraw[];

    const int tid  = threadIdx.x;
    const int lane = tid & 31;
    const int warp = tid >> 5;
    const int g    = lane >> 2;   // 0..7
    const int t    = lane & 3;    // 0..3

    char*   wbase = smraw + warp * WBUF_BYTES;
    unsigned* cbuf = (unsigned*)wbase;                 // [32 rows][32 half2]
    float4* rbuf = (float4*)(wbase + 4096);            // [32] {pa*cc, rs*cc, src, dst}
    float*  ccb  = (float*)(wbase + 4096 + 512);       // [32] cj*ci
    uint2 (*Btab)[4][32] = (uint2(*)[4][32])(smraw + BTAB_OFF);

    // ---- build B fragments once (fp16, single-pass; k = 16ks+4t+{0..3}) ----
    for (int i = tid; i < NT * 4 * 32; i += THREADS) {
        int l  = i & 31;
        int ks = (i >> 5) & 3;
        int nt = i >> 7;
        int gg = l >> 2, tt = l & 3;
        int k0 = 16 * ks + 4 * tt;
        float w0 = 0.f, w1 = 0.f, w2 = 0.f, w3 = 0.f;
        if (nt < 8) {
            const float* W = review_w + (nt * 8 + gg) * OUT_DIM;
            w0 = W[k0]; w1 = W[k0 + 1]; w2 = W[k0 + 2]; w3 = W[k0 + 3];
        } else if (gg == 0) {   // gate col 64 = pa (prob_w)
            w0 = prob_w[k0]; w1 = prob_w[k0 + 1];
            w2 = prob_w[k0 + 2]; w3 = prob_w[k0 + 3];
        } else if (gg == 1) {   // gate col 65 = rs (review_score_w)
            w0 = rsw[k0]; w1 = rsw[k0 + 1];
            w2 = rsw[k0 + 2]; w3 = rsw[k0 + 3];
        }
        Btab[nt][ks][l] = make_uint2(packh2(w0, w1), packh2(w2, w3));
    }
    __syncthreads();

    const int rb = warp * 32;
    const int half = lane >> 4;      // epilogue: 0/1 -> which of 2 rows
    const int j    = lane & 15;      // epilogue: 8B chunk (4 cols) within row

    for (int tile = blockIdx.x; tile < n_tiles; tile += gridDim.x) {
        const int e0 = tile * TILE_E + rb;

        // ---- meta: 1 edge per lane -> ccb, rbuf.zw (src,dst) ----
        {
            int e = e0 + lane;
            bool v = e < E;
            int ec = v ? e : E - 1;
            int s_ = src_idx[ec], d_ = dst_idx[ec];
            float cc = v ? cj[s_] * ci[d_] : 0.f;
            ccb[lane] = cc;
            ((float2*)&rbuf[lane])[1] =
                make_float2(__int_as_float(s_), __int_as_float(d_));
        }
        __syncwarp();

        // ---- load ALL A fragments (16-deep LDG.128.cs burst, streamed) ----
        unsigned a[2][4][4];   // [mt][ks][slot], packed fp16x2
        {
            const float* fA[2];
            const float* fB[2];
            #pragma unroll
            for (int mt = 0; mt < 2; mt++) {
                int ea = e0 + 16 * mt + g;
                int eb = ea + 8;
                fA[mt] = feat + (size_t)(ea < E ? ea : E - 1) * OUT_DIM;
                fB[mt] = feat + (size_t)(eb < E ? eb : E - 1) * OUT_DIM;
            }
            #pragma unroll
            for (int ks = 0; ks < 4; ks++) {
                const int ko = 16 * ks + 4 * t;
                #pragma unroll
                for (int mt = 0; mt < 2; mt++) {
                    float4 v0 = __ldcs((const float4*)(fA[mt] + ko));  // row g
                    float4 v1 = __ldcs((const float4*)(fB[mt] + ko));  // row g+8
                    a[mt][ks][0] = packh2(v0.x, v0.y);
                    a[mt][ks][1] = packh2(v1.x, v1.y);
                    a[mt][ks][2] = packh2(v0.z, v0.w);
                    a[mt][ks][3] = packh2(v1.z, v1.w);
                }
            }
        }

        // ---- GEMM nt-outer, single-pass: 8 accum floats live ----
        #pragma unroll
        for (int nt = 0; nt < NT; nt++) {
            float c0[4] = {0.f, 0.f, 0.f, 0.f};
            float c1[4] = {0.f, 0.f, 0.f, 0.f};
            #pragma unroll
            for (int ks = 0; ks < 4; ks++) {
                uint2 b = Btab[nt][ks][lane];
                mma16816(c0, a[0][ks][0], a[0][ks][1], a[0][ks][2], a[0][ks][3], b.x, b.y);
                mma16816(c1, a[1][ks][0], a[1][ks][1], a[1][ks][2], a[1][ks][3], b.x, b.y);
            }
            if (nt < 8) {
                // slot ch2 = (4nt + t + 4*(r&3)) & 31; one half2 (2 cols) per slot
                {
                    const int r0 = g;
                    const int ch2 = (4 * nt + t + 4 * (r0 & 3)) & 31;
                    cbuf[r0 * 32 + ch2]       = packh2(c0[0], c0[1]);
                    cbuf[(r0 + 8) * 32 + ch2] = packh2(c0[2], c0[3]);
                }
                {
                    const int r0 = 16 + g;
                    const int ch2 = (4 * nt + t + 4 * (r0 & 3)) & 31;
                    cbuf[r0 * 32 + ch2]       = packh2(c1[0], c1[1]);
                    cbuf[(r0 + 8) * 32 + ch2] = packh2(c1[2], c1[3]);
                }
            } else if (t == 0) {
                // gate tile: cols 64(pa), 65(rs); fold sigmoid * cjci
                {
                    const int r0 = g, r1 = g + 8;
                    float cc0 = ccb[r0], cc1 = ccb[r1];
                    ((float2*)&rbuf[r0])[0] = make_float2(
                        sigmoidf_(c0[0]) * cc0, sigmoidf_(c0[1]) * cc0);
                    ((float2*)&rbuf[r1])[0] = make_float2(
                        sigmoidf_(c0[2]) * cc1, sigmoidf_(c0[3]) * cc1);
                }
                {
                    const int r0 = 16 + g, r1 = 24 + g;
                    float cc0 = ccb[r0], cc1 = ccb[r1];
                    ((float2*)&rbuf[r0])[0] = make_float2(
                        sigmoidf_(c1[0]) * cc0, sigmoidf_(c1[1]) * cc0);
                    ((float2*)&rbuf[r1])[0] = make_float2(
                        sigmoidf_(c1[2]) * cc1, sigmoidf_(c1[3]) * cc1);
                }
            }
        }
        __syncwarp();

        // ---- row-major epilogue: 2 edge rows per warp instruction ----
        #pragma unroll
        for (int i = 0; i < 16; i++) {
            const int r = 2 * i + half;
            // slots {2j, 2j+1} = 2 half2 = 4 columns
            uint2 cp = *(const uint2*)(cbuf + r * 32 + 2 * j);
            float2 lo = h2f2(cp.x), hi = h2f2(cp.y);
            const int cn2 = (2 * j - 4 * (r & 3)) & 31;   // even, no pair wrap
            const int col = 2 * cn2;                       // 16B aligned
            float4 q = rbuf[r];                            // {paC, rsC, src, dst}
            int sx = __float_as_int(q.z);
            int dx = __float_as_int(q.w);
            float4 wv = *(const float4*)(weight + (size_t)sx * OUT_DIM + col);
            float4 o;
            o.x = fmaf(wv.x, q.x, lo.x * q.y);
            o.y = fmaf(wv.y, q.x, lo.y * q.y);
            o.z = fmaf(wv.z, q.x, hi.x * q.y);
            o.w = fmaf(wv.w, q.x, hi.y * q.y);
            red_add_v4(out + (size_t)dx * OUT_DIM + col, o);
        }
        __syncwarp();   // buffers reused next tile (warp-private)
    }
}

extern "C" void kernel_launch(void* const* d_in, const int* in_sizes, int n_in,
                              void* d_out, int out_size) {
    const float* weight   = (const float*)d_in[0];
    const float* prob_w   = (const float*)d_in[1];
    const float* rsw      = (const float*)d_in[2];
    const float* review_w = (const float*)d_in[3];
    const float* feat     = (const float*)d_in[4];
    const float* cj       = (const float*)d_in[5];
    const float* ci       = (const float*)d_in[6];
    const int*   src_idx  = (const int*)d_in[7];
    const int*   dst_idx  = (const int*)d_in[8];
    float* out = (float*)d_out;

    const int E = in_sizes[4] / OUT_DIM;
    const int n_tiles = (E + TILE_E - 1) / TILE_E;

    cudaMemsetAsync(d_out, 0, (size_t)out_size * sizeof(float), 0);

    static int smem_set = 0;
    if (!smem_set) {
        cudaFuncSetAttribute(gcmc_kernel,
                             cudaFuncAttributeMaxDynamicSharedMemorySize,
                             SMEM_BYTES);
        smem_set = 1;
    }

    int grid = n_tiles < 444 ? n_tiles : 444;   // 3 persistent blocks / SM
    gcmc_kernel<<<grid, THREADS, SMEM_BYTES, 0>>>(
        weight, prob_w, rsw, review_w, feat, cj, ci, src_idx, dst_idx,
        out, E, n_tiles);
}

// round 15
// speedup vs baseline: 1.2570x; 1.0074x over previous
#include <cuda_runtime.h>
#include <cuda_fp16.h>
#include <cstdint>

// GCMCGraphConv fused kernel v10 (sm_100a) — FINAL (measured 151.2us)
//
//   pa = sigmoid(feat @ prob_w.T); rs = sigmoid(feat @ rsw.T)
//   rf = (feat @ review_w.T) * rs
//   out[d] += (weight[src]*pa + rf) * cj[src] * ci[d]
//
// Session history: 635 (v1 tf32 smem GEMM) -> 437 (fragment-major B) ->
// 244 (direct-GMEM A, fp16 3-pass) -> 197 (warp-private smem transpose
// epilogue) -> 167 (half2 cbuf, occ 3) -> 151 (single-pass fp16 mma).
// Disproven: cp.async staging (v4), meta-hoist (v6), 64-reg/occ-4 diet
// (v11), L2 prefetch (v12), __ldcs (v13, neutral).
//
// Shape: 256 thr x 3 blocks/SM (80 regs), 9 n-tiles (8 rf + 1 gate tile
// computing pa/rs dots on the tensor pipe), warp-private rotation-swizzled
// half2 transpose buffer -> row-major epilogue where weight gather
// (LDG.128) and scatter (red.global.add.v4.f32) touch 2 edge-rows per
// warp instruction. rel_err 3.63e-4 (fp16 single-pass + fp16 cbuf),
// 2.75x under the 1e-3 gate.

#define OUT_DIM 64
#define THREADS 256
#define WARPS   8
#define TILE_E  256
#define NT      9

// per-warp: cbuf 32 rows x 32 half2 (4096B) + rbuf 32xfloat4 (512B) + ccb (128B)
#define WBUF_BYTES  (4096 + 512 + 128)
#define BTAB_OFF    (WARPS * WBUF_BYTES)
#define SMEM_BYTES  (BTAB_OFF + NT * 4 * 32 * 8)

__device__ __forceinline__ void mma16816(float c[4],
    unsigned a0, unsigned a1, unsigned a2, unsigned a3,
    unsigned b0, unsigned b1)
{
    asm volatile(
      "mma.sync.aligned.m16n8k16.row.col.f32.f16.f16.f32 "
      "{%0,%1,%2,%3}, {%4,%5,%6,%7}, {%8,%9}, {%0,%1,%2,%3};\n"
      : "+f"(c[0]), "+f"(c[1]), "+f"(c[2]), "+f"(c[3])
      : "r"(a0), "r"(a1), "r"(a2), "r"(a3), "r"(b0), "r"(b1));
}

__device__ __forceinline__ void red_add_v4(float* p, float4 v) {
    asm volatile("red.global.add.v4.f32 [%0], {%1,%2,%3,%4};"
                 :: "l"(p), "f"(v.x), "f"(v.y), "f"(v.z), "f"(v.w) : "memory");
}

__device__ __forceinline__ unsigned packh2(float a, float b) {
    __half2 h = __floats2half2_rn(a, b);
    return *(unsigned*)&h;
}
__device__ __forceinline__ float2 h2f2(unsigned u) {
    __half2 h = *(__half2*)&u;
    return __half22float2(h);
}
__device__ __forceinline__ float sigmoidf_(float x) {
    return 1.f / (1.f + __expf(-x));
}

__global__ void __launch_bounds__(THREADS, 3)
gcmc_kernel(const float* __restrict__ weight,      // [N_SRC,64]
            const float* __restrict__ prob_w,      // [64]
            const float* __restrict__ rsw,         // [64]
            const float* __restrict__ review_w,    // [64,64]
            const float* __restrict__ feat,        // [E,64]
            const float* __restrict__ cj,          // [N_SRC]
            const float* __restrict__ ci,          // [N_DST]
            const int*   __restrict__ src_idx,     // [E]
            const int*   __restrict__ dst_idx,     // [E]
            float* __restrict__ out,               // [N_DST,64]
            int E, int n_tiles)
{
    extern __shared__ char smraw[];

    const int tid  = threadIdx.x;
    const int lane = tid & 31;
    const int warp = tid >> 5;
    const int g    = lane >> 2;   // 0..7
    const int t    = lane & 3;    // 0..3

    char*   wbase = smraw + warp * WBUF_BYTES;
    unsigned* cbuf = (unsigned*)wbase;                 // [32 rows][32 half2]
    float4* rbuf = (float4*)(wbase + 4096);            // [32] {pa*cc, rs*cc, src, dst}
    float*  ccb  = (float*)(wbase + 4096 + 512);       // [32] cj*ci
    uint2 (*Btab)[4][32] = (uint2(*)[4][32])(smraw + BTAB_OFF);

    // ---- build B fragments once (fp16, single-pass; k = 16ks+4t+{0..3}) ----
    for (int i = tid; i < NT * 4 * 32; i += THREADS) {
        int l  = i & 31;
        int ks = (i >> 5) & 3;
        int nt = i >> 7;
        int gg = l >> 2, tt = l & 3;
        int k0 = 16 * ks + 4 * tt;
        float w0 = 0.f, w1 = 0.f, w2 = 0.f, w3 = 0.f;
        if (nt < 8) {
            const float* W = review_w + (nt * 8 + gg) * OUT_DIM;
            w0 = W[k0]; w1 = W[k0 + 1]; w2 = W[k0 + 2]; w3 = W[k0 + 3];
        } else if (gg == 0) {   // gate col 64 = pa (prob_w)
            w0 = prob_w[k0]; w1 = prob_w[k0 + 1];
            w2 = prob_w[k0 + 2]; w3 = prob_w[k0 + 3];
        } else if (gg == 1) {   // gate col 65 = rs (review_score_w)
            w0 = rsw[k0]; w1 = rsw[k0 + 1];
            w2 = rsw[k0 + 2]; w3 = rsw[k0 + 3];
        }
        Btab[nt][ks][l] = make_uint2(packh2(w0, w1), packh2(w2, w3));
    }
    __syncthreads();

    const int rb = warp * 32;
    const int half = lane >> 4;      // epilogue: 0/1 -> which of 2 rows
    const int j    = lane & 15;      // epilogue: 8B chunk (4 cols) within row

    for (int tile = blockIdx.x; tile < n_tiles; tile += gridDim.x) {
        const int e0 = tile * TILE_E + rb;

        // ---- meta: 1 edge per lane -> ccb, rbuf.zw (src,dst) ----
        {
            int e = e0 + lane;
            bool v = e < E;
            int ec = v ? e : E - 1;
            int s_ = src_idx[ec], d_ = dst_idx[ec];
            float cc = v ? cj[s_] * ci[d_] : 0.f;
            ccb[lane] = cc;
            ((float2*)&rbuf[lane])[1] =
                make_float2(__int_as_float(s_), __int_as_float(d_));
        }
        __syncwarp();

        // ---- load ALL A fragments for this tile (16-deep LDG burst) ----
        unsigned a[2][4][4];   // [mt][ks][slot], packed fp16x2
        {
            const float* fA[2];
            const float* fB[2];
            #pragma unroll
            for (int mt = 0; mt < 2; mt++) {
                int ea = e0 + 16 * mt + g;
                int eb = ea + 8;
                fA[mt] = feat + (size_t)(ea < E ? ea : E - 1) * OUT_DIM;
                fB[mt] = feat + (size_t)(eb < E ? eb : E - 1) * OUT_DIM;
            }
            #pragma unroll
            for (int ks = 0; ks < 4; ks++) {
                const int ko = 16 * ks + 4 * t;
                #pragma unroll
                for (int mt = 0; mt < 2; mt++) {
                    float4 v0 = *(const float4*)(fA[mt] + ko);   // row g
                    float4 v1 = *(const float4*)(fB[mt] + ko);   // row g+8
                    a[mt][ks][0] = packh2(v0.x, v0.y);
                    a[mt][ks][1] = packh2(v1.x, v1.y);
                    a[mt][ks][2] = packh2(v0.z, v0.w);
                    a[mt][ks][3] = packh2(v1.z, v1.w);
                }
            }
        }

        // ---- GEMM nt-outer, single-pass: 8 accum floats live ----
        #pragma unroll
        for (int nt = 0; nt < NT; nt++) {
            float c0[4] = {0.f, 0.f, 0.f, 0.f};
            float c1[4] = {0.f, 0.f, 0.f, 0.f};
            #pragma unroll
            for (int ks = 0; ks < 4; ks++) {
                uint2 b = Btab[nt][ks][lane];
                mma16816(c0, a[0][ks][0], a[0][ks][1], a[0][ks][2], a[0][ks][3], b.x, b.y);
                mma16816(c1, a[1][ks][0], a[1][ks][1], a[1][ks][2], a[1][ks][3], b.x, b.y);
            }
            if (nt < 8) {
                // slot ch2 = (4nt + t + 4*(r&3)) & 31; one half2 (2 cols) per slot
                {
                    const int r0 = g;
                    const int ch2 = (4 * nt + t + 4 * (r0 & 3)) & 31;
                    cbuf[r0 * 32 + ch2]       = packh2(c0[0], c0[1]);
                    cbuf[(r0 + 8) * 32 + ch2] = packh2(c0[2], c0[3]);
                }
                {
                    const int r0 = 16 + g;
                    const int ch2 = (4 * nt + t + 4 * (r0 & 3)) & 31;
                    cbuf[r0 * 32 + ch2]       = packh2(c1[0], c1[1]);
                    cbuf[(r0 + 8) * 32 + ch2] = packh2(c1[2], c1[3]);
                }
            } else if (t == 0) {
                // gate tile: cols 64(pa), 65(rs); fold sigmoid * cjci
                {
                    const int r0 = g, r1 = g + 8;
                    float cc0 = ccb[r0], cc1 = ccb[r1];
                    ((float2*)&rbuf[r0])[0] = make_float2(
                        sigmoidf_(c0[0]) * cc0, sigmoidf_(c0[1]) * cc0);
                    ((float2*)&rbuf[r1])[0] = make_float2(
                        sigmoidf_(c0[2]) * cc1, sigmoidf_(c0[3]) * cc1);
                }
                {
                    const int r0 = 16 + g, r1 = 24 + g;
                    float cc0 = ccb[r0], cc1 = ccb[r1];
                    ((float2*)&rbuf[r0])[0] = make_float2(
                        sigmoidf_(c1[0]) * cc0, sigmoidf_(c1[1]) * cc0);
                    ((float2*)&rbuf[r1])[0] = make_float2(
                        sigmoidf_(c1[2]) * cc1, sigmoidf_(c1[3]) * cc1);
                }
            }
        }
        __syncwarp();

        // ---- row-major epilogue: 2 edge rows per warp instruction ----
        #pragma unroll
        for (int i = 0; i < 16; i++) {
            const int r = 2 * i + half;
            // slots {2j, 2j+1} = 2 half2 = 4 columns
            uint2 cp = *(const uint2*)(cbuf + r * 32 + 2 * j);
            float2 lo = h2f2(cp.x), hi = h2f2(cp.y);
            const int cn2 = (2 * j - 4 * (r & 3)) & 31;   // even, no pair wrap
            const int col = 2 * cn2;                       // 16B aligned
            float4 q = rbuf[r];                            // {paC, rsC, src, dst}
            int sx = __float_as_int(q.z);
            int dx = __float_as_int(q.w);
            float4 wv = *(const float4*)(weight + (size_t)sx * OUT_DIM + col);
            float4 o;
            o.x = fmaf(wv.x, q.x, lo.x * q.y);
            o.y = fmaf(wv.y, q.x, lo.y * q.y);
            o.z = fmaf(wv.z, q.x, hi.x * q.y);
            o.w = fmaf(wv.w, q.x, hi.y * q.y);
            red_add_v4(out + (size_t)dx * OUT_DIM + col, o);
        }
        __syncwarp();   // buffers reused next tile (warp-private)
    }
}

extern "C" void kernel_launch(void* const* d_in, const int* in_sizes, int n_in,
                              void* d_out, int out_size) {
    const float* weight   = (const float*)d_in[0];
    const float* prob_w   = (const float*)d_in[1];
    const float* rsw      = (const float*)d_in[2];
    const float* review_w = (const float*)d_in[3];
    const float* feat     = (const float*)d_in[4];
    const float* cj       = (const float*)d_in[5];
    const float* ci       = (const float*)d_in[6];
    const int*   src_idx  = (const int*)d_in[7];
    const int*   dst_idx  = (const int*)d_in[8];
    float* out = (float*)d_out;

    const int E = in_sizes[4] / OUT_DIM;
    const int n_tiles = (E + TILE_E - 1) / TILE_E;

    cudaMemsetAsync(d_out, 0, (size_t)out_size * sizeof(float), 0);

    static int smem_set = 0;
    if (!smem_set) {
        cudaFuncSetAttribute(gcmc_kernel,
                             cudaFuncAttributeMaxDynamicSharedMemorySize,
                             SMEM_BYTES);
        smem_set = 1;
    }

    int grid = n_tiles < 444 ? n_tiles : 444;   // 3 persistent blocks / SM
    gcmc_kernel<<<grid, THREADS, SMEM_BYTES, 0>>>(
        weight, prob_w, rsw, review_w, feat, cj, ci, src_idx, dst_idx,
        out, E, n_tiles);
}

// round 16
// speedup vs baseline: 1.2592x; 1.0017x over previous
#include <cuda_runtime.h>
#include <cuda_fp16.h>
#include <cstdint>

// GCMCGraphConv fused kernel v10 (sm_100a) — FINAL
// Measured: 151.2us / 151.3us across two independent holds; rel_err 3.632e-4.
//
//   pa = sigmoid(feat @ prob_w.T); rs = sigmoid(feat @ rsw.T)
//   rf = (feat @ review_w.T) * rs
//   out[d] += (weight[src]*pa + rf) * cj[src] * ci[d]
//
// Session: 635 (tf32 smem GEMM) -> 437 (fragment-major B, gate fold) ->
// 244 (direct-GMEM A, fp16 3-pass) -> 197 (warp-private smem-transpose
// epilogue, row-major gather/scatter) -> 167 (half2 cbuf -> occ 3) ->
// 151 (single-pass fp16 mma). Disproven: cp.async staging (v4), meta
// hoist (v6), 64-reg/occ-4 diet (v11), L2 prefetch (v12), __ldcs (v13).
//
// Shape: 256 thr x 3 blocks/SM (80 regs). 9 n-tiles: 8 for rf plus 1
// gate tile computing the pa/rs dot products on the tensor pipe. Accum
// written through a warp-private rotation-swizzled half2 buffer so the
// epilogue is row-major: weight gather (LDG.128) and scatter
// (red.global.add.v4.f32) touch only 2 edge rows per warp instruction.

#define OUT_DIM 64
#define THREADS 256
#define WARPS   8
#define TILE_E  256
#define NT      9

// per-warp: cbuf 32 rows x 32 half2 (4096B) + rbuf 32xfloat4 (512B) + ccb (128B)
#define WBUF_BYTES  (4096 + 512 + 128)
#define BTAB_OFF    (WARPS * WBUF_BYTES)
#define SMEM_BYTES  (BTAB_OFF + NT * 4 * 32 * 8)

__device__ __forceinline__ void mma16816(float c[4],
    unsigned a0, unsigned a1, unsigned a2, unsigned a3,
    unsigned b0, unsigned b1)
{
    asm volatile(
      "mma.sync.aligned.m16n8k16.row.col.f32.f16.f16.f32 "
      "{%0,%1,%2,%3}, {%4,%5,%6,%7}, {%8,%9}, {%0,%1,%2,%3};\n"
      : "+f"(c[0]), "+f"(c[1]), "+f"(c[2]), "+f"(c[3])
      : "r"(a0), "r"(a1), "r"(a2), "r"(a3), "r"(b0), "r"(b1));
}

__device__ __forceinline__ void red_add_v4(float* p, float4 v) {
    asm volatile("red.global.add.v4.f32 [%0], {%1,%2,%3,%4};"
                 :: "l"(p), "f"(v.x), "f"(v.y), "f"(v.z), "f"(v.w) : "memory");
}

__device__ __forceinline__ unsigned packh2(float a, float b) {
    __half2 h = __floats2half2_rn(a, b);
    return *(unsigned*)&h;
}
__device__ __forceinline__ float2 h2f2(unsigned u) {
    __half2 h = *(__half2*)&u;
    return __half22float2(h);
}
__device__ __forceinline__ float sigmoidf_(float x) {
    return 1.f / (1.f + __expf(-x));
}

__global__ void __launch_bounds__(THREADS, 3)
gcmc_kernel(const float* __restrict__ weight,      // [N_SRC,64]
            const float* __restrict__ prob_w,      // [64]
            const float* __restrict__ rsw,         // [64]
            const float* __restrict__ review_w,    // [64,64]
            const float* __restrict__ feat,        // [E,64]
            const float* __restrict__ cj,          // [N_SRC]
            const float* __restrict__ ci,          // [N_DST]
            const int*   __restrict__ src_idx,     // [E]
            const int*   __restrict__ dst_idx,     // [E]
            float* __restrict__ out,               // [N_DST,64]
            int E, int n_tiles)
{
    extern __shared__ char smraw[];

    const int tid  = threadIdx.x;
    const int lane = tid & 31;
    const int warp = tid >> 5;
    const int g    = lane >> 2;   // 0..7
    const int t    = lane & 3;    // 0..3

    char*   wbase = smraw + warp * WBUF_BYTES;
    unsigned* cbuf = (unsigned*)wbase;                 // [32 rows][32 half2]
    float4* rbuf = (float4*)(wbase + 4096);            // [32] {pa*cc, rs*cc, src, dst}
    float*  ccb  = (float*)(wbase + 4096 + 512);       // [32] cj*ci
    uint2 (*Btab)[4][32] = (uint2(*)[4][32])(smraw + BTAB_OFF);

    // ---- build B fragments once (fp16, single-pass; k = 16ks+4t+{0..3}) ----
    for (int i = tid; i < NT * 4 * 32; i += THREADS) {
        int l  = i & 31;
        int ks = (i >> 5) & 3;
        int nt = i >> 7;
        int gg = l >> 2, tt = l & 3;
        int k0 = 16 * ks + 4 * tt;
        float w0 = 0.f, w1 = 0.f, w2 = 0.f, w3 = 0.f;
        if (nt < 8) {
            const float* W = review_w + (nt * 8 + gg) * OUT_DIM;
            w0 = W[k0]; w1 = W[k0 + 1]; w2 = W[k0 + 2]; w3 = W[k0 + 3];
        } else if (gg == 0) {   // gate col 64 = pa (prob_w)
            w0 = prob_w[k0]; w1 = prob_w[k0 + 1];
            w2 = prob_w[k0 + 2]; w3 = prob_w[k0 + 3];
        } else if (gg == 1) {   // gate col 65 = rs (review_score_w)
            w0 = rsw[k0]; w1 = rsw[k0 + 1];
            w2 = rsw[k0 + 2]; w3 = rsw[k0 + 3];
        }
        Btab[nt][ks][l] = make_uint2(packh2(w0, w1), packh2(w2, w3));
    }
    __syncthreads();

    const int rb = warp * 32;
    const int half = lane >> 4;      // epilogue: 0/1 -> which of 2 rows
    const int j    = lane & 15;      // epilogue: 8B chunk (4 cols) within row

    for (int tile = blockIdx.x; tile < n_tiles; tile += gridDim.x) {
        const int e0 = tile * TILE_E + rb;

        // ---- meta: 1 edge per lane -> ccb, rbuf.zw (src,dst) ----
        {
            int e = e0 + lane;
            bool v = e < E;
            int ec = v ? e : E - 1;
            int s_ = src_idx[ec], d_ = dst_idx[ec];
            float cc = v ? cj[s_] * ci[d_] : 0.f;
            ccb[lane] = cc;
            ((float2*)&rbuf[lane])[1] =
                make_float2(__int_as_float(s_), __int_as_float(d_));
        }
        __syncwarp();

        // ---- load ALL A fragments for this tile (16-deep LDG burst) ----
        unsigned a[2][4][4];   // [mt][ks][slot], packed fp16x2
        {
            const float* fA[2];
            const float* fB[2];
            #pragma unroll
            for (int mt = 0; mt < 2; mt++) {
                int ea = e0 + 16 * mt + g;
                int eb = ea + 8;
                fA[mt] = feat + (size_t)(ea < E ? ea : E - 1) * OUT_DIM;
                fB[mt] = feat + (size_t)(eb < E ? eb : E - 1) * OUT_DIM;
            }
            #pragma unroll
            for (int ks = 0; ks < 4; ks++) {
                const int ko = 16 * ks + 4 * t;
                #pragma unroll
                for (int mt = 0; mt < 2; mt++) {
                    float4 v0 = *(const float4*)(fA[mt] + ko);   // row g
                    float4 v1 = *(const float4*)(fB[mt] + ko);   // row g+8
                    a[mt][ks][0] = packh2(v0.x, v0.y);
                    a[mt][ks][1] = packh2(v1.x, v1.y);
                    a[mt][ks][2] = packh2(v0.z, v0.w);
                    a[mt][ks][3] = packh2(v1.z, v1.w);
                }
            }
        }

        // ---- GEMM nt-outer, single-pass: 8 accum floats live ----
        #pragma unroll
        for (int nt = 0; nt < NT; nt++) {
            float c0[4] = {0.f, 0.f, 0.f, 0.f};
            float c1[4] = {0.f, 0.f, 0.f, 0.f};
            #pragma unroll
            for (int ks = 0; ks < 4; ks++) {
                uint2 b = Btab[nt][ks][lane];
                mma16816(c0, a[0][ks][0], a[0][ks][1], a[0][ks][2], a[0][ks][3], b.x, b.y);
                mma16816(c1, a[1][ks][0], a[1][ks][1], a[1][ks][2], a[1][ks][3], b.x, b.y);
            }
            if (nt < 8) {
                // slot ch2 = (4nt + t + 4*(r&3)) & 31; one half2 (2 cols) per slot
                {
                    const int r0 = g;
                    const int ch2 = (4 * nt + t + 4 * (r0 & 3)) & 31;
                    cbuf[r0 * 32 + ch2]       = packh2(c0[0], c0[1]);
                    cbuf[(r0 + 8) * 32 + ch2] = packh2(c0[2], c0[3]);
                }
                {
                    const int r0 = 16 + g;
                    const int ch2 = (4 * nt + t + 4 * (r0 & 3)) & 31;
                    cbuf[r0 * 32 + ch2]       = packh2(c1[0], c1[1]);
                    cbuf[(r0 + 8) * 32 + ch2] = packh2(c1[2], c1[3]);
                }
            } else if (t == 0) {
                // gate tile: cols 64(pa), 65(rs); fold sigmoid * cjci
                {
                    const int r0 = g, r1 = g + 8;
                    float cc0 = ccb[r0], cc1 = ccb[r1];
                    ((float2*)&rbuf[r0])[0] = make_float2(
                        sigmoidf_(c0[0]) * cc0, sigmoidf_(c0[1]) * cc0);
                    ((float2*)&rbuf[r1])[0] = make_float2(
                        sigmoidf_(c0[2]) * cc1, sigmoidf_(c0[3]) * cc1);
                }
                {
                    const int r0 = 16 + g, r1 = 24 + g;
                    float cc0 = ccb[r0], cc1 = ccb[r1];
                    ((float2*)&rbuf[r0])[0] = make_float2(
                        sigmoidf_(c1[0]) * cc0, sigmoidf_(c1[1]) * cc0);
                    ((float2*)&rbuf[r1])[0] = make_float2(
                        sigmoidf_(c1[2]) * cc1, sigmoidf_(c1[3]) * cc1);
                }
            }
        }
        __syncwarp();

        // ---- row-major epilogue: 2 edge rows per warp instruction ----
        #pragma unroll
        for (int i = 0; i < 16; i++) {
            const int r = 2 * i + half;
            // slots {2j, 2j+1} = 2 half2 = 4 columns
            uint2 cp = *(const uint2*)(cbuf + r * 32 + 2 * j);
            float2 lo = h2f2(cp.x), hi = h2f2(cp.y);
            const int cn2 = (2 * j - 4 * (r & 3)) & 31;   // even, no pair wrap
            const int col = 2 * cn2;                       // 16B aligned
            float4 q = rbuf[r];                            // {paC, rsC, src, dst}
            int sx = __float_as_int(q.z);
            int dx = __float_as_int(q.w);
            float4 wv = *(const float4*)(weight + (size_t)sx * OUT_DIM + col);
            float4 o;
            o.x = fmaf(wv.x, q.x, lo.x * q.y);
            o.y = fmaf(wv.y, q.x, lo.y * q.y);
            o.z = fmaf(wv.z, q.x, hi.x * q.y);
            o.w = fmaf(wv.w, q.x, hi.y * q.y);
            red_add_v4(out + (size_t)dx * OUT_DIM + col, o);
        }
        __syncwarp();   // buffers reused next tile (warp-private)
    }
}

extern "C" void kernel_launch(void* const* d_in, const int* in_sizes, int n_in,
                              void* d_out, int out_size) {
    const float* weight   = (const float*)d_in[0];
    const float* prob_w   = (const float*)d_in[1];
    const float* rsw      = (const float*)d_in[2];
    const float* review_w = (const float*)d_in[3];
    const float* feat     = (const float*)d_in[4];
    const float* cj       = (const float*)d_in[5];
    const float* ci       = (const float*)d_in[6];
    const int*   src_idx  = (const int*)d_in[7];
    const int*   dst_idx  = (const int*)d_in[8];
    float* out = (float*)d_out;

    const int E = in_sizes[4] / OUT_DIM;
    const int n_tiles = (E + TILE_E - 1) / TILE_E;

    cudaMemsetAsync(d_out, 0, (size_t)out_size * sizeof(float), 0);

    static int smem_set = 0;
    if (!smem_set) {
        cudaFuncSetAttribute(gcmc_kernel,
                             cudaFuncAttributeMaxDynamicSharedMemorySize,
                             SMEM_BYTES);
        smem_set = 1;
    }

    int grid = n_tiles < 444 ? n_tiles : 444;   // 3 persistent blocks / SM
    gcmc_kernel<<<grid, THREADS, SMEM_BYTES, 0>>>(
        weight, prob_w, rsw, review_w, feat, cj, ci, src_idx, dst_idx,
        out, E, n_tiles);
}